// round 2
// baseline (speedup 1.0000x reference)
#include <cuda_runtime.h>
#include <math.h>

// ---------------------------------------------------------------------------
// HyperGraphEncoder — fp32, FFMA2 (f32x2) GEMMs + persistent GRU recurrence
// B=256 graphs, H=256, 4 heads x 64; padded lens: atom 127, pharm 23, hyper 11
// ---------------------------------------------------------------------------

typedef unsigned long long ull;

namespace {
constexpr int NB   = 256;   // batch (graphs)
constexpr int HD   = 256;   // hidden size H
constexpr int NHEAD = 4;
constexpr int DKH  = 64;    // per-head dim
constexpr int TNA  = 127;   // max atoms
constexpr int TNP  = 23;    // max pharm
constexpr int TNH  = 11;    // max hyper
constexpr int G3   = 768;   // 3*H
constexpr int NBLK = 96;    // persistent kernel blocks (12 n-tiles x 4 m-tiles x 2 dirs)
constexpr int GATE_TOT = 2 * NB * HD;          // 131072 gate elements
constexpr int GATE_THR = NBLK * 256;           // 24576 threads
constexpr int MAXSLOT = (GATE_TOT + GATE_THR - 1) / GATE_THR;  // 6
}

// -------------------------- device scratch ---------------------------------
__device__ float g_atom_f [NB*TNA*HD];
__device__ float g_pharm_f[NB*TNP*HD];
__device__ float g_hyper_f[NB*TNH*HD];
__device__ float g_q1 [NB*TNP*HD];
__device__ float g_k1 [NB*TNH*HD];
__device__ float g_v1 [NB*TNH*HD];
__device__ float g_o1 [NB*TNP*HD];
__device__ float g_pharm2[NB*TNP*HD];
__device__ float g_q2 [NB*TNA*HD];
__device__ float g_k2 [NB*TNP*HD];
__device__ float g_v2 [NB*TNP*HD];
__device__ float g_o2 [NB*TNA*HD];
__device__ float g_h  [NB*TNA*HD];
__device__ float g_gi_f[(size_t)NB*TNA*G3];
__device__ float g_gi_b[(size_t)NB*TNA*G3];
__device__ float g_hcur[2*NB*HD];     // [dir][b][j]
__device__ float g_gh  [2*NB*G3];     // [dir][b][n]
__device__ int   g_starts[3*(NB+1)];
__device__ volatile int g_barctr[2*TNA + 2];   // grid-barrier counters

// -------------------------- f32x2 helpers -----------------------------------
__device__ __forceinline__ ull pk2(float x) {
    ull r; asm("mov.b64 %0,{%1,%1};" : "=l"(r) : "f"(x)); return r;
}
__device__ __forceinline__ void fma2(ull& d, ull a, ull b) {
    asm("fma.rn.f32x2 %0,%1,%2,%0;" : "+l"(d) : "l"(a), "l"(b));
}
__device__ __forceinline__ void unpk2(ull v, float& lo, float& hi) {
    asm("mov.b64 {%0,%1},%2;" : "=f"(lo), "=f"(hi) : "l"(v));
}

// -------------------------- prefix sums ------------------------------------
__global__ void prefix_kernel(const int* __restrict__ ac,
                              const int* __restrict__ pc,
                              const int* __restrict__ hc) {
    int w = threadIdx.x;
    if (w < 3) {
        const int* c = (w == 0) ? ac : (w == 1) ? pc : hc;
        int* s = (int*)(g_starts + w * (NB + 1));
        int acc = 0;
        for (int i = 0; i < NB; i++) { s[i] = acc; acc += c[i]; }
        s[NB] = acc;
    }
}

__global__ void zerobar_kernel() {
    if (threadIdx.x < 2 * TNA + 2) g_barctr[threadIdx.x] = 0;
}

// -------------------------- gather / zero-pad -------------------------------
__global__ void gather_kernel(const float* __restrict__ msg,
                              const int* __restrict__ counts,
                              int which, float* __restrict__ out, int maxN) {
    int j = blockIdx.x, b = blockIdx.y;
    int cnt = counts[b];
    float4* dst = (float4*)(out + ((size_t)b * maxN + j) * HD);
    if (j < cnt) {
        int src_row = g_starts[which * (NB + 1) + b] + j;
        const float4* src = (const float4*)(msg + (size_t)src_row * HD);
        dst[threadIdx.x] = src[threadIdx.x];
    } else {
        dst[threadIdx.x] = make_float4(0.f, 0.f, 0.f, 0.f);
    }
}

// -------------------------- FFMA2 SGEMM (64M x 128N tile, BK=16) -------------
// C[M,N] = A[M,K] @ B (+bias)(+resid).  TRANSB: Bm is [N,K] row-major.
template <bool TRANSB>
__global__ void __launch_bounds__(256)
sgemm2_kernel(const float* __restrict__ A, const float* __restrict__ Bm,
              const float* __restrict__ bias, const float* __restrict__ resid,
              float* __restrict__ C, int M, int N, int K) {
    __shared__ float As[16][64];
    __shared__ float Bs[16][128];
    int m0 = blockIdx.y * 64, n0 = blockIdx.x * 128;
    int tid = threadIdx.x;
    int tx = tid & 15, ty = tid >> 4;
    ull acc[4][4] = {};
    for (int k0 = 0; k0 < K; k0 += 16) {
        {   // A tile
            int row = tid >> 2, seg = tid & 3;
            float4 a = *(const float4*)&A[(size_t)(m0 + row) * K + k0 + seg * 4];
            As[seg*4+0][row] = a.x; As[seg*4+1][row] = a.y;
            As[seg*4+2][row] = a.z; As[seg*4+3][row] = a.w;
        }
        if (!TRANSB) {
            int row = tid >> 4, cs = tid & 15;
            *(float4*)&Bs[row][cs*8]     = *(const float4*)&Bm[(size_t)(k0 + row) * N + n0 + cs*8];
            *(float4*)&Bs[row][cs*8 + 4] = *(const float4*)&Bm[(size_t)(k0 + row) * N + n0 + cs*8 + 4];
        } else {
            int n = tid >> 1, seg = tid & 1;
            float4 b0 = *(const float4*)&Bm[(size_t)(n0 + n) * K + k0 + seg*8];
            float4 b1 = *(const float4*)&Bm[(size_t)(n0 + n) * K + k0 + seg*8 + 4];
            Bs[seg*8+0][n] = b0.x; Bs[seg*8+1][n] = b0.y;
            Bs[seg*8+2][n] = b0.z; Bs[seg*8+3][n] = b0.w;
            Bs[seg*8+4][n] = b1.x; Bs[seg*8+5][n] = b1.y;
            Bs[seg*8+6][n] = b1.z; Bs[seg*8+7][n] = b1.w;
        }
        __syncthreads();
#pragma unroll
        for (int k = 0; k < 16; k++) {
            float4 av = *(const float4*)&As[k][ty * 4];
            ull a0 = pk2(av.x), a1 = pk2(av.y), a2 = pk2(av.z), a3 = pk2(av.w);
            const ulonglong2* bp = (const ulonglong2*)&Bs[k][tx * 8];
            ulonglong2 b01 = bp[0], b23 = bp[1];
            fma2(acc[0][0], a0, b01.x); fma2(acc[0][1], a0, b01.y);
            fma2(acc[0][2], a0, b23.x); fma2(acc[0][3], a0, b23.y);
            fma2(acc[1][0], a1, b01.x); fma2(acc[1][1], a1, b01.y);
            fma2(acc[1][2], a1, b23.x); fma2(acc[1][3], a1, b23.y);
            fma2(acc[2][0], a2, b01.x); fma2(acc[2][1], a2, b01.y);
            fma2(acc[2][2], a2, b23.x); fma2(acc[2][3], a2, b23.y);
            fma2(acc[3][0], a3, b01.x); fma2(acc[3][1], a3, b01.y);
            fma2(acc[3][2], a3, b23.x); fma2(acc[3][3], a3, b23.y);
        }
        __syncthreads();
    }
#pragma unroll
    for (int i = 0; i < 4; i++) {
        int m = m0 + ty * 4 + i;
#pragma unroll
        for (int p = 0; p < 4; p++) {
            int n = n0 + tx * 8 + p * 2;
            float lo, hi;
            unpk2(acc[i][p], lo, hi);
            if (bias)  { lo += bias[n]; hi += bias[n + 1]; }
            if (resid) { float2 rv = *(const float2*)&resid[(size_t)m * N + n];
                         lo += rv.x; hi += rv.y; }
            float2 o; o.x = lo; o.y = hi;
            *(float2*)&C[(size_t)m * N + n] = o;
        }
    }
}

// -------------------------- attention ---------------------------------------
template <int LQ, int LK>
__global__ void attn_kernel(const float* __restrict__ qh,
                            const float* __restrict__ kh,
                            const float* __restrict__ vh,
                            const int* __restrict__ qc,
                            const int* __restrict__ kc,
                            float* __restrict__ o) {
    __shared__ float ks[LK * DKH];
    __shared__ float vs[LK * DKH];
    int bh = blockIdx.x;
    int b = bh / NHEAD, hd = bh % NHEAD;
    for (int idx = threadIdx.x; idx < LK * DKH; idx += blockDim.x) {
        int k = idx / DKH, i = idx % DKH;
        size_t base = ((size_t)(b * LK) + k) * HD + hd * DKH + i;
        ks[idx] = kh[base];
        vs[idx] = vh[base];
    }
    __syncthreads();
    int q = threadIdx.x;
    if (q >= LQ) return;

    float qreg[DKH];
    const float* qp = &qh[((size_t)(b * LQ) + q) * HD + hd * DKH];
#pragma unroll
    for (int i = 0; i < DKH; i++) qreg[i] = qp[i];

    bool vq = q < qc[b];
    int kcnt = kc[b];
    float s[LK];
    float mx = -3.402823e38f;
#pragma unroll
    for (int k = 0; k < LK; k++) {
        float d = 0.f;
#pragma unroll
        for (int i = 0; i < DKH; i++) d = fmaf(qreg[i], ks[k * DKH + i], d);
        float val = (vq && k < kcnt) ? d * 0.125f : -1e9f;
        s[k] = val;
        mx = fmaxf(mx, val);
    }
    float sum = 0.f;
#pragma unroll
    for (int k = 0; k < LK; k++) { s[k] = expf(s[k] - mx); sum += s[k]; }
    float inv = 1.f / sum;
    float* op = &o[((size_t)(b * LQ) + q) * HD + hd * DKH];
#pragma unroll
    for (int i = 0; i < DKH; i++) {
        float a = 0.f;
#pragma unroll
        for (int k = 0; k < LK; k++) a = fmaf(s[k], vs[k * DKH + i], a);
        op[i] = a * inv;
    }
}

// -------------------------- h0 = max over t ---------------------------------
__global__ void hmax_kernel() {
    int b = blockIdx.x, j = threadIdx.x;
    float m = -3.402823e38f;
    for (int t = 0; t < TNA; t++)
        m = fmaxf(m, g_h[((size_t)(b * TNA) + t) * HD + j]);
    g_hcur[(size_t)b * HD + j] = m;
    g_hcur[(size_t)NB * HD + (size_t)b * HD + j] = m;
}

// -------------------------- persistent GRU recurrence -----------------------
__device__ __forceinline__ void gridbar(int i) {
    __syncthreads();
    if (threadIdx.x == 0) {
        __threadfence();
        int v = atomicAdd((int*)&g_barctr[i], 1);
        if (v < NBLK - 1) {
            while (g_barctr[i] < NBLK) { }
        }
        __threadfence();
    }
    __syncthreads();
}

__global__ void __launch_bounds__(256)
gru_persist_kernel(const float* __restrict__ Whh_f, const float* __restrict__ Whh_b,
                   const float* __restrict__ bhh_f, const float* __restrict__ bhh_b,
                   const int* __restrict__ counts, float* __restrict__ out) {
    __shared__ float As[16][64];
    __shared__ float Bs[16][64];
    int bid = blockIdx.x, tid = threadIdx.x;
    int nt = bid % 12;             // n-tile of 64 within 768
    int mt = (bid / 12) & 3;       // m-tile of 64 within 256 batches
    int gd = bid / 48;             // GEMM direction
    const float* Whh = gd ? Whh_b : Whh_f;
    int tx = tid & 15, ty = tid >> 4;

    // ---- gate slot setup (fixed per thread across all steps) ----
    int gidx0 = bid * 256 + tid;
    int nslot = 0;
    int s_d[MAXSLOT], s_b[MAXSLOT], s_j[MAXSLOT], s_cnt[MAXSLOT];
    float hprev[MAXSLOT], osum[MAXSLOT];
    float r_bhh[MAXSLOT][3];
    const float* s_gi[MAXSLOT];
#pragma unroll
    for (int s = 0; s < MAXSLOT; s++) {
        int idx = gidx0 + s * GATE_THR;
        if (idx < GATE_TOT) {
            int dd = idx >> 16, b = (idx >> 8) & 255, j = idx & 255;
            s_d[s] = dd; s_b[s] = b; s_j[s] = j;
            s_cnt[s] = counts[b];
            hprev[s] = g_hcur[(size_t)dd * NB * HD + (size_t)b * HD + j];
            osum[s] = 0.f;
            const float* bhh = dd ? bhh_b : bhh_f;
            r_bhh[s][0] = bhh[j]; r_bhh[s][1] = bhh[j + 256]; r_bhh[s][2] = bhh[j + 512];
            s_gi[s] = (dd ? g_gi_b : g_gi_f) + (size_t)b * TNA * G3 + j;
            nslot = s + 1;
        }
    }

    const float* Abase = g_hcur + (size_t)gd * NB * HD + (size_t)(mt * 64) * HD;
    float* ghbase = g_gh + (size_t)gd * NB * G3;

    for (int t = 0; t < TNA; t++) {
        // ---- GEMM phase: gh[mtile, ntile] = hcur @ Whh^T ----
        ull acc[4][2] = {};
        for (int k0 = 0; k0 < HD; k0 += 16) {
            {
                int row = tid >> 2, seg = tid & 3;
                float4 a = *(const float4*)&Abase[(size_t)row * HD + k0 + seg * 4];
                As[seg*4+0][row] = a.x; As[seg*4+1][row] = a.y;
                As[seg*4+2][row] = a.z; As[seg*4+3][row] = a.w;
            }
            {
                int n = tid >> 2, seg = tid & 3;
                float4 b = *(const float4*)&Whh[(size_t)(nt * 64 + n) * HD + k0 + seg * 4];
                Bs[seg*4+0][n] = b.x; Bs[seg*4+1][n] = b.y;
                Bs[seg*4+2][n] = b.z; Bs[seg*4+3][n] = b.w;
            }
            __syncthreads();
#pragma unroll
            for (int k = 0; k < 16; k++) {
                float4 av = *(const float4*)&As[k][ty * 4];
                ull a0 = pk2(av.x), a1 = pk2(av.y), a2 = pk2(av.z), a3 = pk2(av.w);
                const ulonglong2* bp = (const ulonglong2*)&Bs[k][tx * 4];
                ulonglong2 bv = bp[0];
                fma2(acc[0][0], a0, bv.x); fma2(acc[0][1], a0, bv.y);
                fma2(acc[1][0], a1, bv.x); fma2(acc[1][1], a1, bv.y);
                fma2(acc[2][0], a2, bv.x); fma2(acc[2][1], a2, bv.y);
                fma2(acc[3][0], a3, bv.x); fma2(acc[3][1], a3, bv.y);
            }
            __syncthreads();
        }
#pragma unroll
        for (int i = 0; i < 4; i++) {
            int m = mt * 64 + ty * 4 + i;
#pragma unroll
            for (int p = 0; p < 2; p++) {
                float lo, hi; unpk2(acc[i][p], lo, hi);
                float2 o; o.x = lo; o.y = hi;
                *(float2*)&ghbase[(size_t)m * G3 + nt * 64 + tx * 4 + p * 2] = o;
            }
        }
        gridbar(2 * t);

        // ---- gate phase ----
#pragma unroll
        for (int s = 0; s < MAXSLOT; s++) {
            if (s < nslot) {
                int dd = s_d[s], b = s_b[s], j = s_j[s];
                int teff = dd ? (TNA - 1 - t) : t;
                const float* gi = s_gi[s] + (size_t)teff * G3;
                const float* gh = g_gh + (size_t)dd * NB * G3 + (size_t)b * G3 + j;
                float ir = gi[0], iz = gi[256], in = gi[512];
                float hr = gh[0]   + r_bhh[s][0];
                float hz = gh[256] + r_bhh[s][1];
                float hn = gh[512] + r_bhh[s][2];
                float r = 1.f / (1.f + expf(-(ir + hr)));
                float z = 1.f / (1.f + expf(-(iz + hz)));
                float n = tanhf(in + r * hn);
                float h = (1.f - z) * n + z * hprev[s];
                hprev[s] = h;
                g_hcur[(size_t)dd * NB * HD + (size_t)b * HD + j] = h;
                if (teff < s_cnt[s]) osum[s] += h;
            }
        }
        gridbar(2 * t + 1);
    }

    // ---- final masked mean ----
#pragma unroll
    for (int s = 0; s < MAXSLOT; s++) {
        if (s < nslot) {
            out[(size_t)s_b[s] * 512 + s_d[s] * 256 + s_j[s]] =
                osum[s] / (float)s_cnt[s];
        }
    }
}

// -------------------------- host launch -------------------------------------
static float* symaddr(const void* sym) {
    void* p = nullptr;
    cudaGetSymbolAddress(&p, sym);
    return (float*)p;
}

extern "C" void kernel_launch(void* const* d_in, const int* in_sizes, int n_in,
                              void* d_out, int out_size) {
    int wbase, ci0, ci1, ci2;
    if (in_sizes[3] == NB) { ci0 = 3; ci1 = 4; ci2 = 5; wbase = 6; }
    else { wbase = 3; ci0 = n_in - 3; ci1 = n_in - 2; ci2 = n_in - 1; }

    const float* atom_msg  = (const float*)d_in[0];
    const float* pharm_msg = (const float*)d_in[1];
    const float* hyper_msg = (const float*)d_in[2];
    const int* ac = (const int*)d_in[ci0];
    const int* pc = (const int*)d_in[ci1];
    const int* hc = (const int*)d_in[ci2];

    const float* p2h[8];
    const float* a2p[8];
    for (int i = 0; i < 8; i++) p2h[i] = (const float*)d_in[wbase + i];
    for (int i = 0; i < 8; i++) a2p[i] = (const float*)d_in[wbase + 8 + i];
    const float* Wih_f = (const float*)d_in[wbase + 16];
    const float* Whh_f = (const float*)d_in[wbase + 17];
    const float* bih_f = (const float*)d_in[wbase + 18];
    const float* bhh_f = (const float*)d_in[wbase + 19];
    const float* Wih_b = (const float*)d_in[wbase + 20];
    const float* Whh_b = (const float*)d_in[wbase + 21];
    const float* bih_b = (const float*)d_in[wbase + 22];
    const float* bhh_b = (const float*)d_in[wbase + 23];

    float* atom_f  = symaddr(g_atom_f);
    float* pharm_f = symaddr(g_pharm_f);
    float* hyper_f = symaddr(g_hyper_f);
    float* q1 = symaddr(g_q1);
    float* k1 = symaddr(g_k1);
    float* v1 = symaddr(g_v1);
    float* o1 = symaddr(g_o1);
    float* pharm2 = symaddr(g_pharm2);
    float* q2 = symaddr(g_q2);
    float* k2 = symaddr(g_k2);
    float* v2 = symaddr(g_v2);
    float* o2 = symaddr(g_o2);
    float* hbuf = symaddr(g_h);
    float* gi_f = symaddr(g_gi_f);
    float* gi_b = symaddr(g_gi_b);

    float* out = (float*)d_out;

    const int MA = NB * TNA;   // 32512
    const int MP = NB * TNP;   // 5888
    const int MH = NB * TNH;   // 2816

    prefix_kernel<<<1, 32>>>(ac, pc, hc);
    zerobar_kernel<<<1, 256>>>();

    gather_kernel<<<dim3(TNA, NB), 64>>>(atom_msg,  ac, 0, atom_f,  TNA);
    gather_kernel<<<dim3(TNP, NB), 64>>>(pharm_msg, pc, 1, pharm_f, TNP);
    gather_kernel<<<dim3(TNH, NB), 64>>>(hyper_msg, hc, 2, hyper_f, TNH);

    // MHA1 (pharm queries, hyper kv)
    sgemm2_kernel<false><<<dim3(HD/128, MP/64), 256>>>(pharm_f, p2h[0], p2h[1], nullptr, q1, MP, HD, HD);
    sgemm2_kernel<false><<<dim3(HD/128, MH/64), 256>>>(hyper_f, p2h[2], p2h[3], nullptr, k1, MH, HD, HD);
    sgemm2_kernel<false><<<dim3(HD/128, MH/64), 256>>>(hyper_f, p2h[4], p2h[5], nullptr, v1, MH, HD, HD);
    attn_kernel<TNP, TNH><<<NB * NHEAD, 32>>>(q1, k1, v1, pc, hc, o1);
    sgemm2_kernel<false><<<dim3(HD/128, MP/64), 256>>>(o1, p2h[6], p2h[7], pharm_f, pharm2, MP, HD, HD);

    // MHA2 (atom queries, updated-pharm kv)
    sgemm2_kernel<false><<<dim3(HD/128, MA/64), 256>>>(atom_f, a2p[0], a2p[1], nullptr, q2, MA, HD, HD);
    sgemm2_kernel<false><<<dim3(HD/128, MP/64), 256>>>(pharm2, a2p[2], a2p[3], nullptr, k2, MP, HD, HD);
    sgemm2_kernel<false><<<dim3(HD/128, MP/64), 256>>>(pharm2, a2p[4], a2p[5], nullptr, v2, MP, HD, HD);
    attn_kernel<TNA, TNP><<<NB * NHEAD, 128>>>(q2, k2, v2, ac, pc, o2);
    sgemm2_kernel<false><<<dim3(HD/128, MA/64), 256>>>(o2, a2p[6], a2p[7], atom_f, hbuf, MA, HD, HD);

    // h0 = max over t (both GRU directions)
    hmax_kernel<<<NB, HD>>>();

    // GRU input precompute gi = h @ Wih^T + bih (per direction)
    sgemm2_kernel<true><<<dim3(G3/128, MA/64), 256>>>(hbuf, Wih_f, bih_f, nullptr, gi_f, MA, G3, HD);
    sgemm2_kernel<true><<<dim3(G3/128, MA/64), 256>>>(hbuf, Wih_b, bih_b, nullptr, gi_b, MA, G3, HD);

    // persistent GRU recurrence + masked mean output
    gru_persist_kernel<<<NBLK, 256>>>(Whh_f, Whh_b, bhh_f, bhh_b, ac, out);

    (void)out_size; (void)n_in;
}